// round 1
// baseline (speedup 1.0000x reference)
#include <cuda_runtime.h>
#include <math.h>

// Problem constants
#define Bb 256
#define Tt 200
#define Nh 8
#define Dd 64
#define MODEL 512
#define FFNH 2048
#define ROWS (Bb*Tt)            // 51200
#define EPSV 1.1920929e-07f

// ---------------- scratch (static device globals; no dynamic alloc) ----------
__device__ float d_sn[(size_t)ROWS * MODEL];   // sn, later reused as h
__device__ float d_g1[(size_t)ROWS * FFNH];    // silu(sn@w1)
__device__ float d_g [(size_t)ROWS * FFNH];    // gated = silu(sn@w1)*(sn@w2)
__device__ int   g_mask_is_int32;

// ---------------- mask dtype detection --------------------------------------
// If mask is int32 with values 0/1, bytes at offsets 4i+1..4i+3 are all zero.
// If mask is bool/uint8, those byte positions hold random 0/1 values.
__global__ void detect_mask_kernel(const unsigned char* __restrict__ m) {
    int nz = 0;
    for (int i = 0; i < 64; i++)
        nz |= m[4*i + 1] | m[4*i + 2] | m[4*i + 3];
    g_mask_is_int32 = (nz == 0) ? 1 : 0;
}

// ---------------- RMSNorm ----------------------------------------------------
__global__ __launch_bounds__(128) void rmsnorm_kernel(
    const float* __restrict__ seq, const float* __restrict__ w,
    float* __restrict__ out)
{
    const int row = blockIdx.x;
    const int tid = threadIdx.x;
    const float4* x = (const float4*)(seq + (size_t)row * MODEL);
    float4 xv = x[tid];
    float s = xv.x*xv.x + xv.y*xv.y + xv.z*xv.z + xv.w*xv.w;
    #pragma unroll
    for (int off = 16; off; off >>= 1) s += __shfl_down_sync(0xffffffffu, s, off);
    __shared__ float red[4];
    const int lane = tid & 31, warp = tid >> 5;
    if (lane == 0) red[warp] = s;
    __syncthreads();
    if (tid == 0) {
        float tot = red[0] + red[1] + red[2] + red[3];
        red[0] = rsqrtf(tot * (1.0f / MODEL) + EPSV);
    }
    __syncthreads();
    const float inv = red[0];
    float4 wv = ((const float4*)w)[tid];
    float4 o;
    o.x = xv.x * inv * wv.x;
    o.y = xv.y * inv * wv.y;
    o.z = xv.z * inv * wv.z;
    o.w = xv.w * inv * wv.w;
    ((float4*)(out + (size_t)row * MODEL))[tid] = o;
}

// ---------------- SGEMM: C(MxN) = A(MxK) @ B(KxN), fused epilogue ------------
// MODE 0: C = silu(c)
// MODE 1: C = c * aux
// MODE 2: C = c + aux
template <int MODE>
__global__ __launch_bounds__(256) void sgemm_kernel(
    const float* __restrict__ A, const float* __restrict__ B,
    float* __restrict__ C, const float* __restrict__ aux,
    int M, int N, int K)
{
    __shared__ float As[8][128];
    __shared__ float Bs[8][128];

    const int tid = threadIdx.x;
    const int bx  = blockIdx.x;   // N tile
    const int by  = blockIdx.y;   // M tile
    const int tx  = tid & 15;     // 0..15
    const int ty  = tid >> 4;     // 0..15

    const int aRow = tid >> 1;          // 0..127
    const int aCol = (tid & 1) << 2;    // 0 or 4
    const int bRow = tid >> 5;          // 0..7
    const int bCol = (tid & 31) << 2;   // 0..124

    const float* Ap = A + (size_t)(by*128 + aRow) * K + aCol;
    const float* Bp = B + (size_t)bRow * N + (bx*128 + bCol);

    float acc[8][8];
    #pragma unroll
    for (int i = 0; i < 8; i++)
        #pragma unroll
        for (int j = 0; j < 8; j++) acc[i][j] = 0.0f;

    float4 av = *(const float4*)(Ap);
    float4 bv = *(const float4*)(Bp);

    for (int k0 = 0; k0 < K; k0 += 8) {
        __syncthreads();
        As[aCol+0][aRow] = av.x;
        As[aCol+1][aRow] = av.y;
        As[aCol+2][aRow] = av.z;
        As[aCol+3][aRow] = av.w;
        *(float4*)&Bs[bRow][bCol] = bv;
        __syncthreads();

        if (k0 + 8 < K) {  // prefetch next tiles while computing
            av = *(const float4*)(Ap + k0 + 8);
            bv = *(const float4*)(Bp + (size_t)(k0 + 8) * N);
        }

        #pragma unroll
        for (int k = 0; k < 8; k++) {
            float ra[8], rb[8];
            *(float4*)(ra)   = *(const float4*)&As[k][ty*8];
            *(float4*)(ra+4) = *(const float4*)&As[k][ty*8+4];
            *(float4*)(rb)   = *(const float4*)&Bs[k][tx*8];
            *(float4*)(rb+4) = *(const float4*)&Bs[k][tx*8+4];
            #pragma unroll
            for (int i = 0; i < 8; i++)
                #pragma unroll
                for (int j = 0; j < 8; j++)
                    acc[i][j] = fmaf(ra[i], rb[j], acc[i][j]);
        }
    }

    // epilogue
    #pragma unroll
    for (int i = 0; i < 8; i++) {
        const int row = by*128 + ty*8 + i;
        #pragma unroll
        for (int j4 = 0; j4 < 8; j4 += 4) {
            const int col = bx*128 + tx*8 + j4;
            const size_t idx = (size_t)row * N + col;
            float v[4];
            #pragma unroll
            for (int j = 0; j < 4; j++) {
                float c = acc[i][j4 + j];
                if (MODE == 0) {
                    c = c / (1.0f + __expf(-c));          // silu
                } else if (MODE == 1) {
                    c = c * aux[idx + j];                 // gate multiply
                } else {
                    c = c + aux[idx + j];                 // residual add
                }
                v[j] = c;
            }
            *(float4*)(C + idx) = *(float4*)v;
        }
    }
}

// ---------------- fused single-query attention -------------------------------
// per (n, b): qk = w_k[n] @ q ; s[t] = hh[t,:]·qk * scale (masked);
// softmax; u = Σ_t attn[t]*hh[t,:]; ctx = u @ w_v[n]; out = ctx + q
__global__ __launch_bounds__(128) void attn_kernel(
    const float* __restrict__ q, const float* __restrict__ h,
    const float* __restrict__ wk, const float* __restrict__ wv,
    const void* __restrict__ mask, float* __restrict__ out)
{
    const int n = blockIdx.x;   // head
    const int b = blockIdx.y;   // batch
    const int tid = threadIdx.x;
    const int lane = tid & 31, warp = tid >> 5;

    __shared__ float q_s[64], qk_s[64], s_s[Tt], u_part[2][64], u_s[64], red[4];

    if (tid < 64) q_s[tid] = q[((size_t)b*Nh + n)*Dd + tid];
    __syncthreads();

    if (tid < 64) {
        float a = 0.0f;
        const float* wkp = wk + ((size_t)n*Dd + tid)*Dd;
        #pragma unroll
        for (int e = 0; e < 64; e++) a = fmaf(wkp[e], q_s[e], a);
        qk_s[tid] = a;
    }
    __syncthreads();

    const int mask_int = g_mask_is_int32;
    const float scale = 0.125f;  // 64^-0.5

    for (int t = warp; t < Tt; t += 4) {
        const float* hp = h + ((size_t)(b*Tt + t))*MODEL + n*Dd;
        float p = hp[lane]*qk_s[lane] + hp[lane+32]*qk_s[lane+32];
        #pragma unroll
        for (int off = 16; off; off >>= 1) p += __shfl_down_sync(0xffffffffu, p, off);
        if (lane == 0) {
            bool m;
            if (mask_int) m = ((const int*)mask)[b*Tt + t] != 0;
            else          m = ((const unsigned char*)mask)[b*Tt + t] != 0;
            s_s[t] = m ? p * scale : -INFINITY;
        }
    }
    __syncthreads();

    // softmax: max
    float lm = -INFINITY;
    for (int t = tid; t < Tt; t += 128) lm = fmaxf(lm, s_s[t]);
    #pragma unroll
    for (int off = 16; off; off >>= 1) lm = fmaxf(lm, __shfl_down_sync(0xffffffffu, lm, off));
    if (lane == 0) red[warp] = lm;
    __syncthreads();
    if (tid == 0) red[0] = fmaxf(fmaxf(red[0], red[1]), fmaxf(red[2], red[3]));
    __syncthreads();
    const float mx = red[0];
    __syncthreads();

    // exp + sum
    float ls = 0.0f;
    for (int t = tid; t < Tt; t += 128) {
        float e = __expf(s_s[t] - mx);
        s_s[t] = e;
        ls += e;
    }
    #pragma unroll
    for (int off = 16; off; off >>= 1) ls += __shfl_down_sync(0xffffffffu, ls, off);
    if (lane == 0) red[warp] = ls;
    __syncthreads();
    if (tid == 0) red[0] = red[0] + red[1] + red[2] + red[3];
    __syncthreads();
    const float inv = 1.0f / red[0];
    __syncthreads();

    // u[d] = sum_t attn[t]*hh[t,d]
    const int d = tid & 63, chunk = tid >> 6;  // chunk 0/1
    float acc = 0.0f;
    for (int t = chunk; t < Tt; t += 2)
        acc = fmaf(s_s[t], h[((size_t)(b*Tt + t))*MODEL + n*Dd + d], acc);
    u_part[chunk][d] = acc;
    __syncthreads();
    if (tid < 64) u_s[tid] = (u_part[0][tid] + u_part[1][tid]) * inv;
    __syncthreads();

    // ctx = u @ w_v[n] ; out = ctx + q
    if (tid < 64) {
        float c = 0.0f;
        const float* wvp = wv + (size_t)n*Dd*Dd + tid;
        #pragma unroll
        for (int dd = 0; dd < 64; dd++) c = fmaf(u_s[dd], wvp[dd*Dd], c);
        out[((size_t)b*Nh + n)*Dd + tid] = c + q_s[tid];
    }
}

// ---------------- launch ------------------------------------------------------
extern "C" void kernel_launch(void* const* d_in, const int* in_sizes, int n_in,
                              void* d_out, int out_size)
{
    const float* q    = (const float*)d_in[0];
    const float* seq  = (const float*)d_in[1];
    const float* rmsw = (const float*)d_in[2];
    const float* w1   = (const float*)d_in[3];
    const float* w2   = (const float*)d_in[4];
    const float* w3   = (const float*)d_in[5];
    const float* wk   = (const float*)d_in[6];
    const float* wv   = (const float*)d_in[7];
    const void*  msk  = d_in[8];
    float* out = (float*)d_out;

    float *sn, *g1, *g;
    cudaGetSymbolAddress((void**)&sn, d_sn);
    cudaGetSymbolAddress((void**)&g1, d_g1);
    cudaGetSymbolAddress((void**)&g,  d_g);

    // 1. RMSNorm
    rmsnorm_kernel<<<ROWS, 128>>>(seq, rmsw, sn);
    // 2. silu(sn @ w1)
    sgemm_kernel<0><<<dim3(FFNH/128, ROWS/128), 256>>>(sn, w1, g1, nullptr, ROWS, FFNH, MODEL);
    // 3. gated = (sn @ w2) * silu(sn @ w1)
    sgemm_kernel<1><<<dim3(FFNH/128, ROWS/128), 256>>>(sn, w2, g, g1, ROWS, FFNH, MODEL);
    // 4. h = gated @ w3 + seq   (reuse sn buffer as h)
    sgemm_kernel<2><<<dim3(MODEL/128, ROWS/128), 256>>>(g, w3, sn, seq, ROWS, MODEL, FFNH);
    // 5. mask dtype detect + fused attention
    detect_mask_kernel<<<1, 1>>>((const unsigned char*)msk);
    attn_kernel<<<dim3(Nh, Bb), 128>>>(q, sn, wk, wv, msk, out);
}

// round 3
// speedup vs baseline: 2.4237x; 2.4237x over previous
#include <cuda_runtime.h>
#include <math.h>
#include <stdint.h>

#define Bb 256
#define Tt 200
#define Nh 8
#define Dd 64
#define MODEL 512
#define FFNH 2048
#define ROWS (Bb*Tt)            // 51200
#define EPSV 1.1920929e-07f

// ---------------- scratch ------------------------------------------------------
__device__ float d_sn[(size_t)ROWS * MODEL];   // sn, later reused as h
__device__ float d_g [(size_t)ROWS * FFNH];    // gated FFN activation
__device__ int   g_mask_is_int32;

// ---------------- helpers -------------------------------------------------------
__device__ __forceinline__ uint32_t f2tf(float x) {
    uint32_t r;
    asm("cvt.rna.tf32.f32 %0, %1;" : "=r"(r) : "f"(x));
    return r;
}
__device__ __forceinline__ void mma_tf32(float* c, const uint32_t* a, const uint32_t* b) {
    asm volatile(
        "mma.sync.aligned.m16n8k8.row.col.f32.tf32.tf32.f32 "
        "{%0,%1,%2,%3}, {%4,%5,%6,%7}, {%8,%9}, {%0,%1,%2,%3};"
        : "+f"(c[0]), "+f"(c[1]), "+f"(c[2]), "+f"(c[3])
        : "r"(a[0]), "r"(a[1]), "r"(a[2]), "r"(a[3]), "r"(b[0]), "r"(b[1]));
}

#define LDA 132   // smem row stride (floats): frag LDS bank = (4q+r)%32, conflict-free

// ================================================================================
// Fused GEMM: G = silu(A@W1) * (A@W2)
// A: [ROWS, MODEL] row-major; W1,W2: [MODEL, FFNH] row-major
// block tile: 128 m x 64 n (per matrix), k-step 16, double buffered
// 8 warps = 2(m) x 4(n); warp tile 64m x 16n per matrix
// ================================================================================
__global__ void __launch_bounds__(256, 2) gemm_fused_kernel(
    const float* __restrict__ A, const float* __restrict__ W1,
    const float* __restrict__ W2, float* __restrict__ G)
{
    __shared__ uint32_t As[2][16][LDA];
    __shared__ uint32_t Bs[2][16][LDA];   // cols 0-63: W1, 64-127: W2

    const int tid  = threadIdx.x;
    const int wid  = tid >> 5, lane = tid & 31;
    const int wm   = (wid >> 2) * 64;      // warp m offset
    const int wn   = (wid & 3) * 16;       // warp n offset (within 64)
    const int r    = lane >> 2, q = lane & 3;
    const int m0   = blockIdx.y * 128;
    const int n0   = blockIdx.x * 64;

    // global load indices
    const int am = tid >> 2;               // A: row within tile (two chunks of 64? no: lin)
    const int ak = tid & 3;                // k-group (float4)
    const int bk = tid >> 4;               // W: k row 0..15
    const int bn = tid & 15;               // n float4-chunk 0..15

    float accX[4][2][4], accG[4][2][4];
    #pragma unroll
    for (int i = 0; i < 4; i++)
        #pragma unroll
        for (int j = 0; j < 2; j++)
            #pragma unroll
            for (int v = 0; v < 4; v++) { accX[i][j][v] = 0.f; accG[i][j][v] = 0.f; }

    // prologue: load tile 0
    float4 ar[2], b1r, b2r;
    {
        const float* ap = A + (size_t)(m0)*MODEL;
        ar[0] = *(const float4*)(ap + (size_t)(am)*MODEL + ak*4);
        ar[1] = *(const float4*)(ap + (size_t)(am + 64)*MODEL + ak*4);
        b1r = *(const float4*)(W1 + (size_t)bk*FFNH + n0 + bn*4);
        b2r = *(const float4*)(W2 + (size_t)bk*FFNH + n0 + bn*4);
    }
    {
        const float* a0 = &ar[0].x; const float* a1 = &ar[1].x;
        #pragma unroll
        for (int j = 0; j < 4; j++) {
            As[0][ak*4 + j][am]      = f2tf(a0[j]);
            As[0][ak*4 + j][am + 64] = f2tf(a1[j]);
        }
        const float* p1 = &b1r.x; const float* p2 = &b2r.x;
        #pragma unroll
        for (int j = 0; j < 4; j++) {
            Bs[0][bk][bn*4 + j]      = f2tf(p1[j]);
            Bs[0][bk][64 + bn*4 + j] = f2tf(p2[j]);
        }
    }
    __syncthreads();

    const int NT = MODEL / 16;  // 32
    for (int kt = 0; kt < NT; ++kt) {
        const int cur = kt & 1;
        // prefetch next tile to registers
        if (kt + 1 < NT) {
            const int k0 = (kt + 1) * 16;
            ar[0] = *(const float4*)(A + (size_t)(m0 + am)*MODEL + k0 + ak*4);
            ar[1] = *(const float4*)(A + (size_t)(m0 + am + 64)*MODEL + k0 + ak*4);
            b1r = *(const float4*)(W1 + (size_t)(k0 + bk)*FFNH + n0 + bn*4);
            b2r = *(const float4*)(W2 + (size_t)(k0 + bk)*FFNH + n0 + bn*4);
        }
        // compute on cur
        #pragma unroll
        for (int k8 = 0; k8 < 2; ++k8) {
            const int kb = k8 * 8;
            uint32_t af[4][4];
            #pragma unroll
            for (int mt = 0; mt < 4; mt++) {
                const int m = wm + mt*16 + r;
                af[mt][0] = As[cur][kb + q][m];
                af[mt][1] = As[cur][kb + q][m + 8];
                af[mt][2] = As[cur][kb + q + 4][m];
                af[mt][3] = As[cur][kb + q + 4][m + 8];
            }
            uint32_t bf1[2][2], bf2[2][2];
            #pragma unroll
            for (int nt = 0; nt < 2; nt++) {
                const int n = wn + nt*8 + (lane >> 2);
                bf1[nt][0] = Bs[cur][kb + q][n];
                bf1[nt][1] = Bs[cur][kb + q + 4][n];
                bf2[nt][0] = Bs[cur][kb + q][64 + n];
                bf2[nt][1] = Bs[cur][kb + q + 4][64 + n];
            }
            #pragma unroll
            for (int mt = 0; mt < 4; mt++)
                #pragma unroll
                for (int nt = 0; nt < 2; nt++) {
                    mma_tf32(accX[mt][nt], af[mt], bf1[nt]);
                    mma_tf32(accG[mt][nt], af[mt], bf2[nt]);
                }
        }
        // stage next tile
        if (kt + 1 < NT) {
            const int nb = cur ^ 1;
            const float* a0 = &ar[0].x; const float* a1 = &ar[1].x;
            #pragma unroll
            for (int j = 0; j < 4; j++) {
                As[nb][ak*4 + j][am]      = f2tf(a0[j]);
                As[nb][ak*4 + j][am + 64] = f2tf(a1[j]);
            }
            const float* p1 = &b1r.x; const float* p2 = &b2r.x;
            #pragma unroll
            for (int j = 0; j < 4; j++) {
                Bs[nb][bk][bn*4 + j]      = f2tf(p1[j]);
                Bs[nb][bk][64 + bn*4 + j] = f2tf(p2[j]);
            }
            __syncthreads();
        }
    }

    // epilogue: silu(X)*Gg -> float2 stores
    #pragma unroll
    for (int mt = 0; mt < 4; mt++) {
        #pragma unroll
        for (int nt = 0; nt < 2; nt++) {
            const int col = n0 + wn + nt*8 + 2*q;
            #pragma unroll
            for (int half = 0; half < 2; half++) {
                const int row = m0 + wm + mt*16 + r + half*8;
                float x0 = accX[mt][nt][half*2 + 0], g0 = accG[mt][nt][half*2 + 0];
                float x1 = accX[mt][nt][half*2 + 1], g1 = accG[mt][nt][half*2 + 1];
                float2 o;
                o.x = x0 / (1.f + __expf(-x0)) * g0;
                o.y = x1 / (1.f + __expf(-x1)) * g1;
                *(float2*)(G + (size_t)row*FFNH + col) = o;
            }
        }
    }
}

// ================================================================================
// Out GEMM: H = A@W3 + seq
// A: [ROWS, FFNH]; W3: [FFNH, MODEL]; block 128x128, warp 64x32
// ================================================================================
__global__ void __launch_bounds__(256, 2) gemm_out_kernel(
    const float* __restrict__ A, const float* __restrict__ W3,
    const float* __restrict__ seq, float* __restrict__ H)
{
    __shared__ uint32_t As[2][16][LDA];
    __shared__ uint32_t Bs[2][16][LDA];

    const int tid  = threadIdx.x;
    const int wid  = tid >> 5, lane = tid & 31;
    const int wm   = (wid >> 2) * 64;
    const int wn   = (wid & 3) * 32;
    const int r    = lane >> 2, q = lane & 3;
    const int m0   = blockIdx.y * 128;
    const int n0   = blockIdx.x * 128;

    const int am = tid >> 2, ak = tid & 3;
    const int bk = tid >> 5;               // 0..7 (two chunks)
    const int bn = tid & 31;               // 0..31 float4-chunks

    float acc[4][4][4];
    #pragma unroll
    for (int i = 0; i < 4; i++)
        #pragma unroll
        for (int j = 0; j < 4; j++)
            #pragma unroll
            for (int v = 0; v < 4; v++) acc[i][j][v] = 0.f;

    float4 ar[2], br[2];
    ar[0] = *(const float4*)(A + (size_t)(m0 + am)*FFNH + ak*4);
    ar[1] = *(const float4*)(A + (size_t)(m0 + am + 64)*FFNH + ak*4);
    br[0] = *(const float4*)(W3 + (size_t)bk*MODEL + n0 + bn*4);
    br[1] = *(const float4*)(W3 + (size_t)(bk + 8)*MODEL + n0 + bn*4);
    {
        const float* a0 = &ar[0].x; const float* a1 = &ar[1].x;
        #pragma unroll
        for (int j = 0; j < 4; j++) {
            As[0][ak*4 + j][am]      = f2tf(a0[j]);
            As[0][ak*4 + j][am + 64] = f2tf(a1[j]);
        }
        const float* b0 = &br[0].x; const float* b1 = &br[1].x;
        #pragma unroll
        for (int j = 0; j < 4; j++) {
            Bs[0][bk][bn*4 + j]     = f2tf(b0[j]);
            Bs[0][bk + 8][bn*4 + j] = f2tf(b1[j]);
        }
    }
    __syncthreads();

    const int NT = FFNH / 16;  // 128
    for (int kt = 0; kt < NT; ++kt) {
        const int cur = kt & 1;
        if (kt + 1 < NT) {
            const int k0 = (kt + 1) * 16;
            ar[0] = *(const float4*)(A + (size_t)(m0 + am)*FFNH + k0 + ak*4);
            ar[1] = *(const float4*)(A + (size_t)(m0 + am + 64)*FFNH + k0 + ak*4);
            br[0] = *(const float4*)(W3 + (size_t)(k0 + bk)*MODEL + n0 + bn*4);
            br[1] = *(const float4*)(W3 + (size_t)(k0 + bk + 8)*MODEL + n0 + bn*4);
        }
        #pragma unroll
        for (int k8 = 0; k8 < 2; ++k8) {
            const int kb = k8 * 8;
            uint32_t af[4][4];
            #pragma unroll
            for (int mt = 0; mt < 4; mt++) {
                const int m = wm + mt*16 + r;
                af[mt][0] = As[cur][kb + q][m];
                af[mt][1] = As[cur][kb + q][m + 8];
                af[mt][2] = As[cur][kb + q + 4][m];
                af[mt][3] = As[cur][kb + q + 4][m + 8];
            }
            uint32_t bf[4][2];
            #pragma unroll
            for (int nt = 0; nt < 4; nt++) {
                const int n = wn + nt*8 + (lane >> 2);
                bf[nt][0] = Bs[cur][kb + q][n];
                bf[nt][1] = Bs[cur][kb + q + 4][n];
            }
            #pragma unroll
            for (int mt = 0; mt < 4; mt++)
                #pragma unroll
                for (int nt = 0; nt < 4; nt++)
                    mma_tf32(acc[mt][nt], af[mt], bf[nt]);
        }
        if (kt + 1 < NT) {
            const int nb = cur ^ 1;
            const float* a0 = &ar[0].x; const float* a1 = &ar[1].x;
            #pragma unroll
            for (int j = 0; j < 4; j++) {
                As[nb][ak*4 + j][am]      = f2tf(a0[j]);
                As[nb][ak*4 + j][am + 64] = f2tf(a1[j]);
            }
            const float* b0 = &br[0].x; const float* b1 = &br[1].x;
            #pragma unroll
            for (int j = 0; j < 4; j++) {
                Bs[nb][bk][bn*4 + j]     = f2tf(b0[j]);
                Bs[nb][bk + 8][bn*4 + j] = f2tf(b1[j]);
            }
            __syncthreads();
        }
    }

    // epilogue: + seq residual
    #pragma unroll
    for (int mt = 0; mt < 4; mt++) {
        #pragma unroll
        for (int nt = 0; nt < 4; nt++) {
            const int col = n0 + wn + nt*8 + 2*q;
            #pragma unroll
            for (int half = 0; half < 2; half++) {
                const int row = m0 + wm + mt*16 + r + half*8;
                const float2 s = *(const float2*)(seq + (size_t)row*MODEL + col);
                float2 o;
                o.x = acc[mt][nt][half*2 + 0] + s.x;
                o.y = acc[mt][nt][half*2 + 1] + s.y;
                *(float2*)(H + (size_t)row*MODEL + col) = o;
            }
        }
    }
}

// ---------------- mask dtype detection ----------------------------------------
__global__ void detect_mask_kernel(const unsigned char* __restrict__ m) {
    int nz = 0;
    for (int i = 0; i < 64; i++)
        nz |= m[4*i + 1] | m[4*i + 2] | m[4*i + 3];
    g_mask_is_int32 = (nz == 0) ? 1 : 0;
}

// ---------------- RMSNorm ------------------------------------------------------
__global__ __launch_bounds__(128) void rmsnorm_kernel(
    const float* __restrict__ seq, const float* __restrict__ w,
    float* __restrict__ out)
{
    const int row = blockIdx.x;
    const int tid = threadIdx.x;
    const float4* x = (const float4*)(seq + (size_t)row * MODEL);
    float4 xv = x[tid];
    float s = xv.x*xv.x + xv.y*xv.y + xv.z*xv.z + xv.w*xv.w;
    #pragma unroll
    for (int off = 16; off; off >>= 1) s += __shfl_down_sync(0xffffffffu, s, off);
    __shared__ float red[4];
    const int lane = tid & 31, warp = tid >> 5;
    if (lane == 0) red[warp] = s;
    __syncthreads();
    if (tid == 0) {
        float tot = red[0] + red[1] + red[2] + red[3];
        red[0] = rsqrtf(tot * (1.0f / MODEL) + EPSV);
    }
    __syncthreads();
    const float inv = red[0];
    float4 wv = ((const float4*)w)[tid];
    float4 o;
    o.x = xv.x * inv * wv.x;
    o.y = xv.y * inv * wv.y;
    o.z = xv.z * inv * wv.z;
    o.w = xv.w * inv * wv.w;
    ((float4*)(out + (size_t)row * MODEL))[tid] = o;
}

// ---------------- fused single-query attention ---------------------------------
__global__ __launch_bounds__(128) void attn_kernel(
    const float* __restrict__ q, const float* __restrict__ h,
    const float* __restrict__ wk, const float* __restrict__ wv,
    const void* __restrict__ mask, float* __restrict__ out)
{
    const int n = blockIdx.x;
    const int b = blockIdx.y;
    const int tid = threadIdx.x;
    const int lane = tid & 31, warp = tid >> 5;

    __shared__ float q_s[64], qk_s[64], s_s[Tt], u_part[2][64], u_s[64], red[4];

    if (tid < 64) q_s[tid] = q[((size_t)b*Nh + n)*Dd + tid];
    __syncthreads();

    if (tid < 64) {
        float a = 0.0f;
        const float* wkp = wk + ((size_t)n*Dd + tid)*Dd;
        #pragma unroll
        for (int e = 0; e < 64; e++) a = fmaf(wkp[e], q_s[e], a);
        qk_s[tid] = a;
    }
    __syncthreads();

    const int mask_int = g_mask_is_int32;
    const float scale = 0.125f;

    for (int t = warp; t < Tt; t += 4) {
        const float* hp = h + ((size_t)(b*Tt + t))*MODEL + n*Dd;
        float p = hp[lane]*qk_s[lane] + hp[lane+32]*qk_s[lane+32];
        #pragma unroll
        for (int off = 16; off; off >>= 1) p += __shfl_down_sync(0xffffffffu, p, off);
        if (lane == 0) {
            bool m;
            if (mask_int) m = ((const int*)mask)[b*Tt + t] != 0;
            else          m = ((const unsigned char*)mask)[b*Tt + t] != 0;
            s_s[t] = m ? p * scale : -INFINITY;
        }
    }
    __syncthreads();

    float lm = -INFINITY;
    for (int t = tid; t < Tt; t += 128) lm = fmaxf(lm, s_s[t]);
    #pragma unroll
    for (int off = 16; off; off >>= 1) lm = fmaxf(lm, __shfl_down_sync(0xffffffffu, lm, off));
    if (lane == 0) red[warp] = lm;
    __syncthreads();
    if (tid == 0) red[0] = fmaxf(fmaxf(red[0], red[1]), fmaxf(red[2], red[3]));
    __syncthreads();
    const float mx = red[0];
    __syncthreads();

    float ls = 0.0f;
    for (int t = tid; t < Tt; t += 128) {
        float e = __expf(s_s[t] - mx);
        s_s[t] = e;
        ls += e;
    }
    #pragma unroll
    for (int off = 16; off; off >>= 1) ls += __shfl_down_sync(0xffffffffu, ls, off);
    if (lane == 0) red[warp] = ls;
    __syncthreads();
    if (tid == 0) red[0] = red[0] + red[1] + red[2] + red[3];
    __syncthreads();
    const float inv = 1.0f / red[0];
    __syncthreads();

    const int d = tid & 63, chunk = tid >> 6;
    float acc = 0.0f;
    for (int t = chunk; t < Tt; t += 2)
        acc = fmaf(s_s[t], h[((size_t)(b*Tt + t))*MODEL + n*Dd + d], acc);
    u_part[chunk][d] = acc;
    __syncthreads();
    if (tid < 64) u_s[tid] = (u_part[0][tid] + u_part[1][tid]) * inv;
    __syncthreads();

    if (tid < 64) {
        float c = 0.0f;
        const float* wvp = wv + (size_t)n*Dd*Dd + tid;
        #pragma unroll
        for (int dd = 0; dd < 64; dd++) c = fmaf(u_s[dd], wvp[dd*Dd], c);
        out[((size_t)b*Nh + n)*Dd + tid] = c + q_s[tid];
    }
}

// ---------------- launch ---------------------------------------------------------
extern "C" void kernel_launch(void* const* d_in, const int* in_sizes, int n_in,
                              void* d_out, int out_size)
{
    const float* q    = (const float*)d_in[0];
    const float* seq  = (const float*)d_in[1];
    const float* rmsw = (const float*)d_in[2];
    const float* w1   = (const float*)d_in[3];
    const float* w2   = (const float*)d_in[4];
    const float* w3   = (const float*)d_in[5];
    const float* wk   = (const float*)d_in[6];
    const float* wv   = (const float*)d_in[7];
    const void*  msk  = d_in[8];
    float* out = (float*)d_out;

    float *sn, *g;
    cudaGetSymbolAddress((void**)&sn, d_sn);
    cudaGetSymbolAddress((void**)&g,  d_g);

    rmsnorm_kernel<<<ROWS, 128>>>(seq, rmsw, sn);
    gemm_fused_kernel<<<dim3(FFNH/64, ROWS/128), 256>>>(sn, w1, w2, g);
    gemm_out_kernel<<<dim3(MODEL/128, ROWS/128), 256>>>(g, w3, seq, sn);
    detect_mask_kernel<<<1, 1>>>((const unsigned char*)msk);
    attn_kernel<<<dim3(Nh, Bb), 128>>>(q, sn, wk, wv, msk, out);
}

// round 4
// speedup vs baseline: 4.8806x; 2.0137x over previous
#include <cuda_runtime.h>
#include <cuda_bf16.h>
#include <math.h>
#include <stdint.h>

#define Bb 256
#define Tt 200
#define Nh 8
#define Dd 64
#define MODEL 512
#define FFNH 2048
#define ROWS (Bb*Tt)            // 51200
#define EPSV 1.1920929e-07f

// ---------------- scratch (static device globals) ------------------------------
__device__ __nv_bfloat16 d_snb[(size_t)ROWS * MODEL];  // rmsnorm output (bf16)
__device__ __nv_bfloat16 d_g [(size_t)ROWS * FFNH];    // gated FFN activation (bf16)
__device__ float         d_h [(size_t)ROWS * MODEL];   // FFN output + residual (fp32)

// ---------------- helpers --------------------------------------------------------
__device__ __forceinline__ uint32_t packbf(float lo, float hi) {
    __nv_bfloat162 t = __floats2bfloat162_rn(lo, hi);   // .x = lo (k even), .y = hi
    return *reinterpret_cast<uint32_t*>(&t);
}
__device__ __forceinline__ void mma_bf16(float* c, const uint32_t* a, const uint32_t* b) {
    asm volatile(
        "mma.sync.aligned.m16n8k16.row.col.f32.bf16.bf16.f32 "
        "{%0,%1,%2,%3}, {%4,%5,%6,%7}, {%8,%9}, {%0,%1,%2,%3};"
        : "+f"(c[0]), "+f"(c[1]), "+f"(c[2]), "+f"(c[3])
        : "r"(a[0]), "r"(a[1]), "r"(a[2]), "r"(a[3]), "r"(b[0]), "r"(b[1]));
}

// SMEM geometry (uint32 = one bf16x2 k-pair)
#define PADA 20    // A row stride: bank = (20r + q) % 32, all-distinct
#define PADB 136   // B pair-row stride: bank = (8q + r) % 32, all-distinct
#define A_WORDS (128*PADA)     // per buffer: 2560
#define B_WORDS (16*PADB)      // per buffer: 2176

// ================================================================================
// Fused GEMM1: G = bf16( silu(A@W1) * (A@W2) )
// A: [ROWS, MODEL] bf16; W1,W2: [MODEL, FFNH] fp32
// block 128m x 64n (per matrix), k-step 32; 8 warps = 2m x 4n; warp 64m x 16n
// ================================================================================
__global__ void __launch_bounds__(256, 2) gemm_fused_kernel(
    const __nv_bfloat16* __restrict__ A, const float* __restrict__ W1,
    const float* __restrict__ W2, __nv_bfloat16* __restrict__ G)
{
    extern __shared__ uint32_t sm[];
    uint32_t* As  = sm;                       // [2][128][PADA]
    uint32_t* Bs1 = sm + 2*A_WORDS;           // [2][16][PADB]
    uint32_t* Bs2 = Bs1 + 2*B_WORDS;

    const int tid = threadIdx.x;
    const int wid = tid >> 5, lane = tid & 31;
    const int wm = (wid >> 2) * 64, wn = (wid & 3) * 16;
    const int r = lane >> 2, q = lane & 3;
    const int m0 = blockIdx.y * 128, n0 = blockIdx.x * 64;

    const int arow = tid >> 1, ahalf = tid & 1;       // A: 2 threads/row, 32B each
    const int bp = tid >> 4, bn = (tid & 15) * 4;     // B: pair-row bp, 4 cols

    float accX[4][2][4], accG[4][2][4];
    #pragma unroll
    for (int i = 0; i < 4; i++)
        #pragma unroll
        for (int j = 0; j < 2; j++)
            #pragma unroll
            for (int v = 0; v < 4; v++) { accX[i][j][v] = 0.f; accG[i][j][v] = 0.f; }

    uint4 av0, av1;
    float4 b1lo, b1hi, b2lo, b2hi;

    // prologue loads (k0 = 0)
    {
        const __nv_bfloat16* ap = A + (size_t)(m0 + arow)*MODEL + ahalf*16;
        av0 = *(const uint4*)(ap);
        av1 = *(const uint4*)(ap + 8);
        b1lo = *(const float4*)(W1 + (size_t)(2*bp  )*FFNH + n0 + bn);
        b1hi = *(const float4*)(W1 + (size_t)(2*bp+1)*FFNH + n0 + bn);
        b2lo = *(const float4*)(W2 + (size_t)(2*bp  )*FFNH + n0 + bn);
        b2hi = *(const float4*)(W2 + (size_t)(2*bp+1)*FFNH + n0 + bn);
    }
    // stage buffer 0
    {
        *(uint4*)(As + arow*PADA + ahalf*8)     = av0;
        *(uint4*)(As + arow*PADA + ahalf*8 + 4) = av1;
        uint4 p1, p2;
        p1.x = packbf(b1lo.x, b1hi.x); p1.y = packbf(b1lo.y, b1hi.y);
        p1.z = packbf(b1lo.z, b1hi.z); p1.w = packbf(b1lo.w, b1hi.w);
        p2.x = packbf(b2lo.x, b2hi.x); p2.y = packbf(b2lo.y, b2hi.y);
        p2.z = packbf(b2lo.z, b2hi.z); p2.w = packbf(b2lo.w, b2hi.w);
        *(uint4*)(Bs1 + bp*PADB + bn) = p1;
        *(uint4*)(Bs2 + bp*PADB + bn) = p2;
    }
    __syncthreads();

    const int NT = MODEL / 32;  // 16
    for (int kt = 0; kt < NT; ++kt) {
        const int cur = kt & 1;
        if (kt + 1 < NT) {
            const int k0 = (kt + 1) * 32;
            const __nv_bfloat16* ap = A + (size_t)(m0 + arow)*MODEL + k0 + ahalf*16;
            av0 = *(const uint4*)(ap);
            av1 = *(const uint4*)(ap + 8);
            b1lo = *(const float4*)(W1 + (size_t)(k0 + 2*bp  )*FFNH + n0 + bn);
            b1hi = *(const float4*)(W1 + (size_t)(k0 + 2*bp+1)*FFNH + n0 + bn);
            b2lo = *(const float4*)(W2 + (size_t)(k0 + 2*bp  )*FFNH + n0 + bn);
            b2hi = *(const float4*)(W2 + (size_t)(k0 + 2*bp+1)*FFNH + n0 + bn);
        }
        const uint32_t* Ab  = As  + cur*A_WORDS;
        const uint32_t* B1b = Bs1 + cur*B_WORDS;
        const uint32_t* B2b = Bs2 + cur*B_WORDS;
        #pragma unroll
        for (int k8 = 0; k8 < 2; ++k8) {
            const int kb = k8 * 8;
            uint32_t af[4][4];
            #pragma unroll
            for (int mt = 0; mt < 4; mt++) {
                const int m = wm + mt*16 + r;
                af[mt][0] = Ab[(m    )*PADA + kb + q];
                af[mt][1] = Ab[(m + 8)*PADA + kb + q];
                af[mt][2] = Ab[(m    )*PADA + kb + q + 4];
                af[mt][3] = Ab[(m + 8)*PADA + kb + q + 4];
            }
            uint32_t bf1[2][2], bf2[2][2];
            #pragma unroll
            for (int nt = 0; nt < 2; nt++) {
                const int n = wn + nt*8 + r;
                bf1[nt][0] = B1b[(kb + q    )*PADB + n];
                bf1[nt][1] = B1b[(kb + q + 4)*PADB + n];
                bf2[nt][0] = B2b[(kb + q    )*PADB + n];
                bf2[nt][1] = B2b[(kb + q + 4)*PADB + n];
            }
            #pragma unroll
            for (int mt = 0; mt < 4; mt++)
                #pragma unroll
                for (int nt = 0; nt < 2; nt++) {
                    mma_bf16(accX[mt][nt], af[mt], bf1[nt]);
                    mma_bf16(accG[mt][nt], af[mt], bf2[nt]);
                }
        }
        if (kt + 1 < NT) {
            const int nb = cur ^ 1;
            *(uint4*)(As + nb*A_WORDS + arow*PADA + ahalf*8)     = av0;
            *(uint4*)(As + nb*A_WORDS + arow*PADA + ahalf*8 + 4) = av1;
            uint4 p1, p2;
            p1.x = packbf(b1lo.x, b1hi.x); p1.y = packbf(b1lo.y, b1hi.y);
            p1.z = packbf(b1lo.z, b1hi.z); p1.w = packbf(b1lo.w, b1hi.w);
            p2.x = packbf(b2lo.x, b2hi.x); p2.y = packbf(b2lo.y, b2hi.y);
            p2.z = packbf(b2lo.z, b2hi.z); p2.w = packbf(b2lo.w, b2hi.w);
            *(uint4*)(Bs1 + nb*B_WORDS + bp*PADB + bn) = p1;
            *(uint4*)(Bs2 + nb*B_WORDS + bp*PADB + bn) = p2;
            __syncthreads();
        }
    }

    // epilogue: silu(X)*G -> bf16x2 stores
    #pragma unroll
    for (int mt = 0; mt < 4; mt++) {
        #pragma unroll
        for (int nt = 0; nt < 2; nt++) {
            const int col = n0 + wn + nt*8 + 2*q;
            #pragma unroll
            for (int half = 0; half < 2; half++) {
                const int row = m0 + wm + mt*16 + r + half*8;
                const float x0 = accX[mt][nt][half*2 + 0], g0 = accG[mt][nt][half*2 + 0];
                const float x1 = accX[mt][nt][half*2 + 1], g1 = accG[mt][nt][half*2 + 1];
                const float o0 = x0 / (1.f + __expf(-x0)) * g0;
                const float o1 = x1 / (1.f + __expf(-x1)) * g1;
                __nv_bfloat162 st = __floats2bfloat162_rn(o0, o1);
                *(__nv_bfloat162*)(G + (size_t)row*FFNH + col) = st;
            }
        }
    }
}

// ================================================================================
// GEMM2: H = A@W3 + seq   (fp32 out)
// A: [ROWS, FFNH] bf16; W3: [FFNH, MODEL] fp32; block 128x128, warp 64x32
// ================================================================================
__global__ void __launch_bounds__(256, 2) gemm_out_kernel(
    const __nv_bfloat16* __restrict__ A, const float* __restrict__ W3,
    const float* __restrict__ seq, float* __restrict__ H)
{
    extern __shared__ uint32_t sm[];
    uint32_t* As = sm;                  // [2][128][PADA]
    uint32_t* Bs = sm + 2*A_WORDS;      // [2][16][PADB], n = 0..127

    const int tid = threadIdx.x;
    const int wid = tid >> 5, lane = tid & 31;
    const int wm = (wid >> 2) * 64, wn = (wid & 3) * 32;
    const int r = lane >> 2, q = lane & 3;
    const int m0 = blockIdx.y * 128, n0 = blockIdx.x * 128;

    const int arow = tid >> 1, ahalf = tid & 1;
    const int bp = tid >> 4, bn = (tid & 15) * 8;

    float acc[4][4][4];
    #pragma unroll
    for (int i = 0; i < 4; i++)
        #pragma unroll
        for (int j = 0; j < 4; j++)
            #pragma unroll
            for (int v = 0; v < 4; v++) acc[i][j][v] = 0.f;

    uint4 av0, av1;
    float4 blo0, blo1, bhi0, bhi1;
    {
        const __nv_bfloat16* ap = A + (size_t)(m0 + arow)*FFNH + ahalf*16;
        av0 = *(const uint4*)(ap);
        av1 = *(const uint4*)(ap + 8);
        blo0 = *(const float4*)(W3 + (size_t)(2*bp  )*MODEL + n0 + bn);
        blo1 = *(const float4*)(W3 + (size_t)(2*bp  )*MODEL + n0 + bn + 4);
        bhi0 = *(const float4*)(W3 + (size_t)(2*bp+1)*MODEL + n0 + bn);
        bhi1 = *(const float4*)(W3 + (size_t)(2*bp+1)*MODEL + n0 + bn + 4);
    }
    {
        *(uint4*)(As + arow*PADA + ahalf*8)     = av0;
        *(uint4*)(As + arow*PADA + ahalf*8 + 4) = av1;
        uint4 p0, p1;
        p0.x = packbf(blo0.x, bhi0.x); p0.y = packbf(blo0.y, bhi0.y);
        p0.z = packbf(blo0.z, bhi0.z); p0.w = packbf(blo0.w, bhi0.w);
        p1.x = packbf(blo1.x, bhi1.x); p1.y = packbf(blo1.y, bhi1.y);
        p1.z = packbf(blo1.z, bhi1.z); p1.w = packbf(blo1.w, bhi1.w);
        *(uint4*)(Bs + bp*PADB + bn)     = p0;
        *(uint4*)(Bs + bp*PADB + bn + 4) = p1;
    }
    __syncthreads();

    const int NT = FFNH / 32;  // 64
    for (int kt = 0; kt < NT; ++kt) {
        const int cur = kt & 1;
        if (kt + 1 < NT) {
            const int k0 = (kt + 1) * 32;
            const __nv_bfloat16* ap = A + (size_t)(m0 + arow)*FFNH + k0 + ahalf*16;
            av0 = *(const uint4*)(ap);
            av1 = *(const uint4*)(ap + 8);
            blo0 = *(const float4*)(W3 + (size_t)(k0 + 2*bp  )*MODEL + n0 + bn);
            blo1 = *(const float4*)(W3 + (size_t)(k0 + 2*bp  )*MODEL + n0 + bn + 4);
            bhi0 = *(const float4*)(W3 + (size_t)(k0 + 2*bp+1)*MODEL + n0 + bn);
            bhi1 = *(const float4*)(W3 + (size_t)(k0 + 2*bp+1)*MODEL + n0 + bn + 4);
        }
        const uint32_t* Ab = As + cur*A_WORDS;
        const uint32_t* Bbf = Bs + cur*B_WORDS;
        #pragma unroll
        for (int k8 = 0; k8 < 2; ++k8) {
            const int kb = k8 * 8;
            uint32_t af[4][4];
            #pragma unroll
            for (int mt = 0; mt < 4; mt++) {
                const int m = wm + mt*16 + r;
                af[mt][0] = Ab[(m    )*PADA + kb + q];
                af[mt][1] = Ab[(m + 8)*PADA + kb + q];
                af[mt][2] = Ab[(m    )*PADA + kb + q + 4];
                af[mt][3] = Ab[(m + 8)*PADA + kb + q + 4];
            }
            uint32_t bf[4][2];
            #pragma unroll
            for (int nt = 0; nt < 4; nt++) {
                const int n = wn + nt*8 + r;
                bf[nt][0] = Bbf[(kb + q    )*PADB + n];
                bf[nt][1] = Bbf[(kb + q + 4)*PADB + n];
            }
            #pragma unroll
            for (int mt = 0; mt < 4; mt++)
                #pragma unroll
                for (int nt = 0; nt < 4; nt++)
                    mma_bf16(acc[mt][nt], af[mt], bf[nt]);
        }
        if (kt + 1 < NT) {
            const int nb = cur ^ 1;
            *(uint4*)(As + nb*A_WORDS + arow*PADA + ahalf*8)     = av0;
            *(uint4*)(As + nb*A_WORDS + arow*PADA + ahalf*8 + 4) = av1;
            uint4 p0, p1;
            p0.x = packbf(blo0.x, bhi0.x); p0.y = packbf(blo0.y, bhi0.y);
            p0.z = packbf(blo0.z, bhi0.z); p0.w = packbf(blo0.w, bhi0.w);
            p1.x = packbf(blo1.x, bhi1.x); p1.y = packbf(blo1.y, bhi1.y);
            p1.z = packbf(blo1.z, bhi1.z); p1.w = packbf(blo1.w, bhi1.w);
            *(uint4*)(Bs + nb*B_WORDS + bp*PADB + bn)     = p0;
            *(uint4*)(Bs + nb*B_WORDS + bp*PADB + bn + 4) = p1;
            __syncthreads();
        }
    }

    // epilogue: + seq residual (fp32)
    #pragma unroll
    for (int mt = 0; mt < 4; mt++) {
        #pragma unroll
        for (int nt = 0; nt < 4; nt++) {
            const int col = n0 + wn + nt*8 + 2*q;
            #pragma unroll
            for (int half = 0; half < 2; half++) {
                const int row = m0 + wm + mt*16 + r + half*8;
                const float2 s = *(const float2*)(seq + (size_t)row*MODEL + col);
                float2 o;
                o.x = acc[mt][nt][half*2 + 0] + s.x;
                o.y = acc[mt][nt][half*2 + 1] + s.y;
                *(float2*)(H + (size_t)row*MODEL + col) = o;
            }
        }
    }
}

// ---------------- RMSNorm (fp32 in -> bf16 out) ---------------------------------
__global__ __launch_bounds__(128) void rmsnorm_kernel(
    const float* __restrict__ seq, const float* __restrict__ w,
    __nv_bfloat16* __restrict__ out)
{
    const int row = blockIdx.x;
    const int tid = threadIdx.x;
    const float4 xv = ((const float4*)(seq + (size_t)row * MODEL))[tid];
    float s = xv.x*xv.x + xv.y*xv.y + xv.z*xv.z + xv.w*xv.w;
    #pragma unroll
    for (int off = 16; off; off >>= 1) s += __shfl_down_sync(0xffffffffu, s, off);
    __shared__ float red[4];
    const int lane = tid & 31, warp = tid >> 5;
    if (lane == 0) red[warp] = s;
    __syncthreads();
    if (tid == 0) {
        float tot = red[0] + red[1] + red[2] + red[3];
        red[0] = rsqrtf(tot * (1.0f / MODEL) + EPSV);
    }
    __syncthreads();
    const float inv = red[0];
    const float4 wv = ((const float4*)w)[tid];
    __nv_bfloat162 o0 = __floats2bfloat162_rn(xv.x*inv*wv.x, xv.y*inv*wv.y);
    __nv_bfloat162 o1 = __floats2bfloat162_rn(xv.z*inv*wv.z, xv.w*inv*wv.w);
    uint2 st;
    st.x = *(uint32_t*)&o0;
    st.y = *(uint32_t*)&o1;
    ((uint2*)(out + (size_t)row * MODEL))[tid] = st;
}

// ---------------- fused single-query attention -----------------------------------
__global__ __launch_bounds__(128) void attn_kernel(
    const float* __restrict__ q, const float* __restrict__ h,
    const float* __restrict__ wk, const float* __restrict__ wv,
    const void* __restrict__ mask, float* __restrict__ out)
{
    const int n = blockIdx.x;
    const int b = blockIdx.y;
    const int tid = threadIdx.x;
    const int lane = tid & 31, warp = tid >> 5;

    __shared__ float q_s[64], qk_s[64], s_s[Tt], u_part[2][64], u_s[64], red[4];
    __shared__ int mz[4];

    // inline mask-dtype detection (int32 0/1 => high bytes of first 64 ints all 0)
    int nz = 0;
    if (tid < 64) {
        const unsigned char* mb = (const unsigned char*)mask;
        nz = mb[4*tid + 1] | mb[4*tid + 2] | mb[4*tid + 3];
    }
    const int wany = __any_sync(0xffffffffu, nz != 0) ? 1 : 0;
    if (lane == 0) mz[warp] = wany;

    if (tid < 64) q_s[tid] = q[((size_t)b*Nh + n)*Dd + tid];
    __syncthreads();

    const int mask_int = !(mz[0] | mz[1]);

    if (tid < 64) {
        float a = 0.0f;
        const float* wkp = wk + ((size_t)n*Dd + tid)*Dd;
        #pragma unroll
        for (int e = 0; e < 64; e++) a = fmaf(wkp[e], q_s[e], a);
        qk_s[tid] = a;
    }
    __syncthreads();

    const float scale = 0.125f;

    for (int t = warp; t < Tt; t += 4) {
        const float* hp = h + ((size_t)(b*Tt + t))*MODEL + n*Dd;
        float p = hp[lane]*qk_s[lane] + hp[lane+32]*qk_s[lane+32];
        #pragma unroll
        for (int off = 16; off; off >>= 1) p += __shfl_down_sync(0xffffffffu, p, off);
        if (lane == 0) {
            bool m;
            if (mask_int) m = ((const int*)mask)[b*Tt + t] != 0;
            else          m = ((const unsigned char*)mask)[b*Tt + t] != 0;
            s_s[t] = m ? p * scale : -INFINITY;
        }
    }
    __syncthreads();

    float lm = -INFINITY;
    for (int t = tid; t < Tt; t += 128) lm = fmaxf(lm, s_s[t]);
    #pragma unroll
    for (int off = 16; off; off >>= 1) lm = fmaxf(lm, __shfl_down_sync(0xffffffffu, lm, off));
    if (lane == 0) red[warp] = lm;
    __syncthreads();
    if (tid == 0) red[0] = fmaxf(fmaxf(red[0], red[1]), fmaxf(red[2], red[3]));
    __syncthreads();
    const float mx = red[0];
    __syncthreads();

    float ls = 0.0f;
    for (int t = tid; t < Tt; t += 128) {
        float e = __expf(s_s[t] - mx);
        s_s[t] = e;
        ls += e;
    }
    #pragma unroll
    for (int off = 16; off; off >>= 1) ls += __shfl_down_sync(0xffffffffu, ls, off);
    if (lane == 0) red[warp] = ls;
    __syncthreads();
    if (tid == 0) red[0] = red[0] + red[1] + red[2] + red[3];
    __syncthreads();
    const float inv = 1.0f / red[0];
    __syncthreads();

    const int d = tid & 63, chunk = tid >> 6;
    float acc = 0.0f;
    for (int t = chunk; t < Tt; t += 2)
        acc = fmaf(s_s[t], h[((size_t)(b*Tt + t))*MODEL + n*Dd + d], acc);
    u_part[chunk][d] = acc;
    __syncthreads();
    if (tid < 64) u_s[tid] = (u_part[0][tid] + u_part[1][tid]) * inv;
    __syncthreads();

    if (tid < 64) {
        float c = 0.0f;
        const float* wvp = wv + (size_t)n*Dd*Dd + tid;
        #pragma unroll
        for (int dd = 0; dd < 64; dd++) c = fmaf(u_s[dd], wvp[dd*Dd], c);
        out[((size_t)b*Nh + n)*Dd + tid] = c + q_s[tid];
    }
}

// ---------------- launch -----------------------------------------------------------
extern "C" void kernel_launch(void* const* d_in, const int* in_sizes, int n_in,
                              void* d_out, int out_size)
{
    const float* q    = (const float*)d_in[0];
    const float* seq  = (const float*)d_in[1];
    const float* rmsw = (const float*)d_in[2];
    const float* w1   = (const float*)d_in[3];
    const float* w2   = (const float*)d_in[4];
    const float* w3   = (const float*)d_in[5];
    const float* wk   = (const float*)d_in[6];
    const float* wv   = (const float*)d_in[7];
    const void*  msk  = d_in[8];
    float* out = (float*)d_out;

    __nv_bfloat16 *snb, *g;
    float *h;
    cudaGetSymbolAddress((void**)&snb, d_snb);
    cudaGetSymbolAddress((void**)&g,   d_g);
    cudaGetSymbolAddress((void**)&h,   d_h);

    const int SMEM1 = (2*A_WORDS + 4*B_WORDS) * 4;   // 55296 B
    const int SMEM2 = (2*A_WORDS + 2*B_WORDS) * 4;   // 37888 B
    cudaFuncSetAttribute(gemm_fused_kernel, cudaFuncAttributeMaxDynamicSharedMemorySize, SMEM1);
    cudaFuncSetAttribute(gemm_out_kernel,   cudaFuncAttributeMaxDynamicSharedMemorySize, SMEM2);

    rmsnorm_kernel<<<ROWS, 128>>>(seq, rmsw, snb);
    gemm_fused_kernel<<<dim3(FFNH/64, ROWS/128), 256, SMEM1>>>(snb, w1, w2, g);
    gemm_out_kernel<<<dim3(MODEL/128, ROWS/128), 256, SMEM2>>>(g, w3, seq, h);
    attn_kernel<<<dim3(Nh, Bb), 128>>>(q, h, wk, wv, msk, out);
}

// round 5
// speedup vs baseline: 7.3133x; 1.4984x over previous
#include <cuda_runtime.h>
#include <cuda_bf16.h>
#include <math.h>
#include <stdint.h>

#define Bb 256
#define Tt 200
#define Nh 8
#define Dd 64
#define MODEL 512
#define FFNH 2048
#define ROWS (Bb*Tt)            // 51200
#define EPSV 1.1920929e-07f

// ---------------- scratch (static device globals) ------------------------------
__device__ __nv_bfloat16 d_snb[(size_t)ROWS * MODEL];   // rmsnorm output (bf16)
__device__ __nv_bfloat16 d_g [(size_t)ROWS * FFNH];     // gated FFN activation (bf16)
__device__ float         d_h [(size_t)ROWS * MODEL];    // FFN output + residual (fp32)
__device__ __nv_bfloat16 d_w1b[MODEL * FFNH];
__device__ __nv_bfloat16 d_w2b[MODEL * FFNH];
__device__ __nv_bfloat16 d_w3b[FFNH * MODEL];

// ---------------- PTX helpers ----------------------------------------------------
__device__ __forceinline__ uint32_t smem_u32(const void* p) {
    uint32_t a;
    asm("{ .reg .u64 t; cvta.to.shared.u64 t, %1; cvt.u32.u64 %0, t; }" : "=r"(a) : "l"(p));
    return a;
}
#define CP_ASYNC(dst, src) asm volatile("cp.async.cg.shared.global [%0], [%1], 16;" :: "r"(dst), "l"(src))
#define CP_COMMIT()        asm volatile("cp.async.commit_group;" ::: "memory")
#define CP_WAIT1()         asm volatile("cp.async.wait_group 1;" ::: "memory")

#define LDMX4(r, addr) asm volatile( \
    "ldmatrix.sync.aligned.m8n8.x4.shared.b16 {%0,%1,%2,%3}, [%4];" \
    : "=r"((r)[0]), "=r"((r)[1]), "=r"((r)[2]), "=r"((r)[3]) : "r"(addr))
#define LDMX4T(r, addr) asm volatile( \
    "ldmatrix.sync.aligned.m8n8.x4.trans.shared.b16 {%0,%1,%2,%3}, [%4];" \
    : "=r"((r)[0]), "=r"((r)[1]), "=r"((r)[2]), "=r"((r)[3]) : "r"(addr))

__device__ __forceinline__ void mma_bf16(float* c, const uint32_t* a, const uint32_t* b) {
    asm volatile(
        "mma.sync.aligned.m16n8k16.row.col.f32.bf16.bf16.f32 "
        "{%0,%1,%2,%3}, {%4,%5,%6,%7}, {%8,%9}, {%0,%1,%2,%3};"
        : "+f"(c[0]), "+f"(c[1]), "+f"(c[2]), "+f"(c[3])
        : "r"(a[0]), "r"(a[1]), "r"(a[2]), "r"(a[3]), "r"(b[0]), "r"(b[1]));
}

// ---------------- weight fp32 -> bf16 pack ---------------------------------------
__global__ __launch_bounds__(256) void pack_w_kernel(
    const float* __restrict__ in, __nv_bfloat16* __restrict__ out, int n4)
{
    const int i = blockIdx.x * 256 + threadIdx.x;
    if (i < n4) {
        const float4 v = *(const float4*)(in + (size_t)i*4);
        __nv_bfloat162 lo = __floats2bfloat162_rn(v.x, v.y);
        __nv_bfloat162 hi = __floats2bfloat162_rn(v.z, v.w);
        uint2 st;
        st.x = *(uint32_t*)&lo;
        st.y = *(uint32_t*)&hi;
        *(uint2*)(out + (size_t)i*4) = st;
    }
}

// ================================================================================
// GEMM1: G = bf16( silu(A@W1) * (A@W2) )
// A: [ROWS, 512] bf16; W1,W2: [512, 2048] bf16
// block 128m x 64n(x2), k-step 64, 3-stage cp.async; 8 warps 2m x 4n; warp 64x16x2
// SMEM: A 3x16KB @0; B1 3x8KB @49152; B2 3x8KB @73728  (total 96KB)
// ================================================================================
__global__ void __launch_bounds__(256, 2) gemm_fused_kernel(
    const __nv_bfloat16* __restrict__ A, const __nv_bfloat16* __restrict__ W1,
    const __nv_bfloat16* __restrict__ W2, __nv_bfloat16* __restrict__ G)
{
    extern __shared__ char sm[];
    const uint32_t sb = smem_u32(sm);
    const int tid = threadIdx.x;
    const int wid = tid >> 5, lane = tid & 31;
    const int wm = (wid >> 2) * 64, wn = (wid & 3) * 16;
    const int m0 = blockIdx.y * 128, n0 = blockIdx.x * 64;

    float accX[4][2][4], accG[4][2][4];
    #pragma unroll
    for (int i = 0; i < 4; i++)
        #pragma unroll
        for (int j = 0; j < 2; j++)
            #pragma unroll
            for (int v = 0; v < 4; v++) { accX[i][j][v] = 0.f; accG[i][j][v] = 0.f; }

    auto issue = [&](int st, int k0) {
        const uint32_t sA  = sb + (uint32_t)st*16384u;
        const uint32_t sB1 = sb + 49152u + (uint32_t)st*8192u;
        const uint32_t sB2 = sb + 73728u + (uint32_t)st*8192u;
        const int arow = tid >> 1;
        const __nv_bfloat16* ag = A + (size_t)(m0 + arow)*MODEL + k0 + (tid & 1)*32;
        const uint32_t abase = sA + (uint32_t)arow*128u;
        #pragma unroll
        for (int j = 0; j < 4; j++) {
            const int c = (tid & 1)*4 + j;
            CP_ASYNC(abase + (uint32_t)((c ^ (arow & 7)) << 4), ag + j*8);
        }
        const int brow = tid >> 2;
        const __nv_bfloat16* b1g = W1 + (size_t)(k0 + brow)*FFNH + n0 + (tid & 3)*16;
        const __nv_bfloat16* b2g = W2 + (size_t)(k0 + brow)*FFNH + n0 + (tid & 3)*16;
        const uint32_t b1base = sB1 + (uint32_t)brow*128u;
        const uint32_t b2base = sB2 + (uint32_t)brow*128u;
        #pragma unroll
        for (int j = 0; j < 2; j++) {
            const int c = (tid & 3)*2 + j;
            const uint32_t sw = (uint32_t)((c ^ (brow & 7)) << 4);
            CP_ASYNC(b1base + sw, b1g + j*8);
            CP_ASYNC(b2base + sw, b2g + j*8);
        }
        CP_COMMIT();
    };

    issue(0, 0);
    issue(1, 64);

    const int NT = MODEL / 64;  // 8
    for (int kt = 0; kt < NT; ++kt) {
        CP_WAIT1();
        __syncthreads();
        const int cur = kt % 3;
        if (kt + 2 < NT) issue((kt + 2) % 3, (kt + 2)*64); else CP_COMMIT();

        const uint32_t sA  = sb + (uint32_t)cur*16384u;
        const uint32_t sB1 = sb + 49152u + (uint32_t)cur*8192u;
        const uint32_t sB2 = sb + 73728u + (uint32_t)cur*8192u;

        #pragma unroll
        for (int k16 = 0; k16 < 4; ++k16) {
            uint32_t af[4][4];
            #pragma unroll
            for (int mt = 0; mt < 4; mt++) {
                const int row = wm + mt*16 + (lane & 15);
                const uint32_t a = sA + (uint32_t)row*128u
                    + (uint32_t)((((k16*2 + (lane >> 4)) ^ (row & 7))) << 4);
                LDMX4(af[mt], a);
            }
            uint32_t b1[4], b2[4];
            {
                const int krow = k16*16 + (lane & 15);
                const int nch = (wid & 3)*2 + (lane >> 4);
                const uint32_t off = (uint32_t)krow*128u + (uint32_t)((nch ^ (lane & 7)) << 4);
                LDMX4T(b1, sB1 + off);
                LDMX4T(b2, sB2 + off);
            }
            #pragma unroll
            for (int mt = 0; mt < 4; mt++)
                #pragma unroll
                for (int nt = 0; nt < 2; nt++) {
                    mma_bf16(accX[mt][nt], af[mt], &b1[nt*2]);
                    mma_bf16(accG[mt][nt], af[mt], &b2[nt*2]);
                }
        }
    }

    // epilogue: silu(X)*G -> bf16x2
    const int r = lane >> 2, q = lane & 3;
    #pragma unroll
    for (int mt = 0; mt < 4; mt++) {
        #pragma unroll
        for (int nt = 0; nt < 2; nt++) {
            const int col = n0 + wn + nt*8 + 2*q;
            #pragma unroll
            for (int half = 0; half < 2; half++) {
                const int row = m0 + wm + mt*16 + r + half*8;
                const float x0 = accX[mt][nt][half*2 + 0], g0 = accG[mt][nt][half*2 + 0];
                const float x1 = accX[mt][nt][half*2 + 1], g1 = accG[mt][nt][half*2 + 1];
                const float o0 = x0 / (1.f + __expf(-x0)) * g0;
                const float o1 = x1 / (1.f + __expf(-x1)) * g1;
                __nv_bfloat162 st = __floats2bfloat162_rn(o0, o1);
                *(__nv_bfloat162*)(G + (size_t)row*FFNH + col) = st;
            }
        }
    }
}

// ================================================================================
// GEMM2: H = A@W3 + seq  (fp32 out)
// A: [ROWS, 2048] bf16; W3: [2048, 512] bf16; block 128x128, k-step 64, 3 stages
// SMEM: A 3x16KB @0; B 3x16KB @49152 (total 96KB); 8 warps 2m x 4n; warp 64x32
// ================================================================================
__global__ void __launch_bounds__(256, 2) gemm_out_kernel(
    const __nv_bfloat16* __restrict__ A, const __nv_bfloat16* __restrict__ W3,
    const float* __restrict__ seq, float* __restrict__ H)
{
    extern __shared__ char sm[];
    const uint32_t sb = smem_u32(sm);
    const int tid = threadIdx.x;
    const int wid = tid >> 5, lane = tid & 31;
    const int wm = (wid >> 2) * 64, wn = (wid & 3) * 32;
    const int m0 = blockIdx.y * 128, n0 = blockIdx.x * 128;

    float acc[4][4][4];
    #pragma unroll
    for (int i = 0; i < 4; i++)
        #pragma unroll
        for (int j = 0; j < 4; j++)
            #pragma unroll
            for (int v = 0; v < 4; v++) acc[i][j][v] = 0.f;

    auto issue = [&](int st, int k0) {
        const uint32_t sA = sb + (uint32_t)st*16384u;
        const uint32_t sB = sb + 49152u + (uint32_t)st*16384u;
        const int arow = tid >> 1;
        const __nv_bfloat16* ag = A + (size_t)(m0 + arow)*FFNH + k0 + (tid & 1)*32;
        const uint32_t abase = sA + (uint32_t)arow*128u;
        #pragma unroll
        for (int j = 0; j < 4; j++) {
            const int c = (tid & 1)*4 + j;
            CP_ASYNC(abase + (uint32_t)((c ^ (arow & 7)) << 4), ag + j*8);
        }
        const int brow = tid >> 2;
        const __nv_bfloat16* bg = W3 + (size_t)(k0 + brow)*MODEL + n0 + (tid & 3)*32;
        const uint32_t bbase = sB + (uint32_t)brow*256u;
        #pragma unroll
        for (int j = 0; j < 4; j++) {
            const int c = (tid & 3)*4 + j;
            CP_ASYNC(bbase + (uint32_t)((c ^ (brow & 7)) << 4), bg + j*8);
        }
        CP_COMMIT();
    };

    issue(0, 0);
    issue(1, 64);

    const int NT = FFNH / 64;  // 32
    for (int kt = 0; kt < NT; ++kt) {
        CP_WAIT1();
        __syncthreads();
        const int cur = kt % 3;
        if (kt + 2 < NT) issue((kt + 2) % 3, (kt + 2)*64); else CP_COMMIT();

        const uint32_t sA = sb + (uint32_t)cur*16384u;
        const uint32_t sB = sb + 49152u + (uint32_t)cur*16384u;

        #pragma unroll
        for (int k16 = 0; k16 < 4; ++k16) {
            uint32_t af[4][4];
            #pragma unroll
            for (int mt = 0; mt < 4; mt++) {
                const int row = wm + mt*16 + (lane & 15);
                const uint32_t a = sA + (uint32_t)row*128u
                    + (uint32_t)((((k16*2 + (lane >> 4)) ^ (row & 7))) << 4);
                LDMX4(af[mt], a);
            }
            uint32_t bf[8];
            {
                const int krow = k16*16 + (lane & 15);
                const uint32_t rowoff = (uint32_t)krow*256u;
                #pragma unroll
                for (int hh = 0; hh < 2; hh++) {
                    const int nch = (wid & 3)*4 + hh*2 + (lane >> 4);
                    LDMX4T(&bf[hh*4], sB + rowoff + (uint32_t)((nch ^ (lane & 7)) << 4));
                }
            }
            #pragma unroll
            for (int mt = 0; mt < 4; mt++)
                #pragma unroll
                for (int nt = 0; nt < 4; nt++)
                    mma_bf16(acc[mt][nt], af[mt], &bf[nt*2]);
        }
    }

    // epilogue: + seq residual
    const int r = lane >> 2, q = lane & 3;
    #pragma unroll
    for (int mt = 0; mt < 4; mt++) {
        #pragma unroll
        for (int nt = 0; nt < 4; nt++) {
            const int col = n0 + wn + nt*8 + 2*q;
            #pragma unroll
            for (int half = 0; half < 2; half++) {
                const int row = m0 + wm + mt*16 + r + half*8;
                const float2 s = *(const float2*)(seq + (size_t)row*MODEL + col);
                float2 o;
                o.x = acc[mt][nt][half*2 + 0] + s.x;
                o.y = acc[mt][nt][half*2 + 1] + s.y;
                *(float2*)(H + (size_t)row*MODEL + col) = o;
            }
        }
    }
}

// ---------------- RMSNorm (fp32 in -> bf16 out) -----------------------------------
__global__ __launch_bounds__(128) void rmsnorm_kernel(
    const float* __restrict__ seq, const float* __restrict__ w,
    __nv_bfloat16* __restrict__ out)
{
    const int row = blockIdx.x;
    const int tid = threadIdx.x;
    const float4 xv = ((const float4*)(seq + (size_t)row * MODEL))[tid];
    float s = xv.x*xv.x + xv.y*xv.y + xv.z*xv.z + xv.w*xv.w;
    #pragma unroll
    for (int off = 16; off; off >>= 1) s += __shfl_down_sync(0xffffffffu, s, off);
    __shared__ float red[4];
    const int lane = tid & 31, warp = tid >> 5;
    if (lane == 0) red[warp] = s;
    __syncthreads();
    if (tid == 0) {
        float tot = red[0] + red[1] + red[2] + red[3];
        red[0] = rsqrtf(tot * (1.0f / MODEL) + EPSV);
    }
    __syncthreads();
    const float inv = red[0];
    const float4 wv = ((const float4*)w)[tid];
    __nv_bfloat162 o0 = __floats2bfloat162_rn(xv.x*inv*wv.x, xv.y*inv*wv.y);
    __nv_bfloat162 o1 = __floats2bfloat162_rn(xv.z*inv*wv.z, xv.w*inv*wv.w);
    uint2 st;
    st.x = *(uint32_t*)&o0;
    st.y = *(uint32_t*)&o1;
    ((uint2*)(out + (size_t)row * MODEL))[tid] = st;
}

// ---------------- fused single-query attention -------------------------------------
__global__ __launch_bounds__(128) void attn_kernel(
    const float* __restrict__ q, const float* __restrict__ h,
    const float* __restrict__ wk, const float* __restrict__ wv,
    const void* __restrict__ mask, float* __restrict__ out)
{
    const int n = blockIdx.x;
    const int b = blockIdx.y;
    const int tid = threadIdx.x;
    const int lane = tid & 31, warp = tid >> 5;

    __shared__ float q_s[64], qk_s[64], s_s[Tt], u_part[2][64], u_s[64], red[4];
    __shared__ int mz[4];

    int nz = 0;
    if (tid < 64) {
        const unsigned char* mb = (const unsigned char*)mask;
        nz = mb[4*tid + 1] | mb[4*tid + 2] | mb[4*tid + 3];
    }
    const int wany = __any_sync(0xffffffffu, nz != 0) ? 1 : 0;
    if (lane == 0) mz[warp] = wany;

    if (tid < 64) q_s[tid] = q[((size_t)b*Nh + n)*Dd + tid];
    __syncthreads();

    const int mask_int = !(mz[0] | mz[1]);

    if (tid < 64) {
        float a = 0.0f;
        const float* wkp = wk + ((size_t)n*Dd + tid)*Dd;
        #pragma unroll
        for (int e = 0; e < 64; e++) a = fmaf(wkp[e], q_s[e], a);
        qk_s[tid] = a;
    }
    __syncthreads();

    const float scale = 0.125f;

    for (int t = warp; t < Tt; t += 4) {
        const float* hp = h + ((size_t)(b*Tt + t))*MODEL + n*Dd;
        float p = hp[lane]*qk_s[lane] + hp[lane+32]*qk_s[lane+32];
        #pragma unroll
        for (int off = 16; off; off >>= 1) p += __shfl_down_sync(0xffffffffu, p, off);
        if (lane == 0) {
            bool m;
            if (mask_int) m = ((const int*)mask)[b*Tt + t] != 0;
            else          m = ((const unsigned char*)mask)[b*Tt + t] != 0;
            s_s[t] = m ? p * scale : -INFINITY;
        }
    }
    __syncthreads();

    float lm = -INFINITY;
    for (int t = tid; t < Tt; t += 128) lm = fmaxf(lm, s_s[t]);
    #pragma unroll
    for (int off = 16; off; off >>= 1) lm = fmaxf(lm, __shfl_down_sync(0xffffffffu, lm, off));
    if (lane == 0) red[warp] = lm;
    __syncthreads();
    if (tid == 0) red[0] = fmaxf(fmaxf(red[0], red[1]), fmaxf(red[2], red[3]));
    __syncthreads();
    const float mx = red[0];
    __syncthreads();

    float ls = 0.0f;
    for (int t = tid; t < Tt; t += 128) {
        float e = __expf(s_s[t] - mx);
        s_s[t] = e;
        ls += e;
    }
    #pragma unroll
    for (int off = 16; off; off >>= 1) ls += __shfl_down_sync(0xffffffffu, ls, off);
    if (lane == 0) red[warp] = ls;
    __syncthreads();
    if (tid == 0) red[0] = red[0] + red[1] + red[2] + red[3];
    __syncthreads();
    const float inv = 1.0f / red[0];
    __syncthreads();

    const int d = tid & 63, chunk = tid >> 6;
    float acc = 0.0f;
    for (int t = chunk; t < Tt; t += 2)
        acc = fmaf(s_s[t], h[((size_t)(b*Tt + t))*MODEL + n*Dd + d], acc);
    u_part[chunk][d] = acc;
    __syncthreads();
    if (tid < 64) u_s[tid] = (u_part[0][tid] + u_part[1][tid]) * inv;
    __syncthreads();

    if (tid < 64) {
        float c = 0.0f;
        const float* wvp = wv + (size_t)n*Dd*Dd + tid;
        #pragma unroll
        for (int dd = 0; dd < 64; dd++) c = fmaf(u_s[dd], wvp[dd*Dd], c);
        out[((size_t)b*Nh + n)*Dd + tid] = c + q_s[tid];
    }
}

// ---------------- launch -------------------------------------------------------------
extern "C" void kernel_launch(void* const* d_in, const int* in_sizes, int n_in,
                              void* d_out, int out_size)
{
    const float* q    = (const float*)d_in[0];
    const float* seq  = (const float*)d_in[1];
    const float* rmsw = (const float*)d_in[2];
    const float* w1   = (const float*)d_in[3];
    const float* w2   = (const float*)d_in[4];
    const float* w3   = (const float*)d_in[5];
    const float* wk   = (const float*)d_in[6];
    const float* wv   = (const float*)d_in[7];
    const void*  msk  = d_in[8];
    float* out = (float*)d_out;

    __nv_bfloat16 *snb, *g, *w1b, *w2b, *w3b;
    float *h;
    cudaGetSymbolAddress((void**)&snb, d_snb);
    cudaGetSymbolAddress((void**)&g,   d_g);
    cudaGetSymbolAddress((void**)&h,   d_h);
    cudaGetSymbolAddress((void**)&w1b, d_w1b);
    cudaGetSymbolAddress((void**)&w2b, d_w2b);
    cudaGetSymbolAddress((void**)&w3b, d_w3b);

    const int SMEM = 98304;   // 96 KB per block, 2 blocks/SM
    cudaFuncSetAttribute(gemm_fused_kernel, cudaFuncAttributeMaxDynamicSharedMemorySize, SMEM);
    cudaFuncSetAttribute(gemm_out_kernel,   cudaFuncAttributeMaxDynamicSharedMemorySize, SMEM);

    const int W4 = (MODEL*FFNH)/4;   // 262144 float4s per weight
    pack_w_kernel<<<(W4 + 255)/256, 256>>>(w1, w1b, W4);
    pack_w_kernel<<<(W4 + 255)/256, 256>>>(w2, w2b, W4);
    pack_w_kernel<<<(W4 + 255)/256, 256>>>(w3, w3b, W4);

    rmsnorm_kernel<<<ROWS, 128>>>(seq, rmsw, snb);
    gemm_fused_kernel<<<dim3(FFNH/64, ROWS/128), 256, SMEM>>>(snb, w1b, w2b, g);
    gemm_out_kernel<<<dim3(MODEL/128, ROWS/128), 256, SMEM>>>(g, w3b, seq, h);
    attn_kernel<<<dim3(Nh, Bb), 128>>>(q, h, wk, wv, msk, out);
}

// round 6
// speedup vs baseline: 7.5276x; 1.0293x over previous
#include <cuda_runtime.h>
#include <cuda_bf16.h>
#include <math.h>
#include <stdint.h>

#define Bb 256
#define Tt 200
#define Nh 8
#define Dd 64
#define MODEL 512
#define FFNH 2048
#define ROWS (Bb*Tt)            // 51200
#define EPSV 1.1920929e-07f

// ---------------- scratch (static device globals) ------------------------------
__device__ __nv_bfloat16 d_snb[(size_t)ROWS * MODEL];   // rmsnorm output (bf16)
__device__ __nv_bfloat16 d_g [(size_t)ROWS * FFNH];     // gated FFN activation (bf16)
__device__ float         d_h [(size_t)ROWS * MODEL];    // FFN output + residual (fp32)
__device__ __nv_bfloat16 d_w1b[MODEL * FFNH];
__device__ __nv_bfloat16 d_w2b[MODEL * FFNH];
__device__ __nv_bfloat16 d_w3b[FFNH * MODEL];

// ---------------- PTX helpers ----------------------------------------------------
__device__ __forceinline__ uint32_t smem_u32(const void* p) {
    uint32_t a;
    asm("{ .reg .u64 t; cvta.to.shared.u64 t, %1; cvt.u32.u64 %0, t; }" : "=r"(a) : "l"(p));
    return a;
}
#define CP_ASYNC(dst, src) asm volatile("cp.async.cg.shared.global [%0], [%1], 16;" :: "r"(dst), "l"(src))
#define CP_COMMIT()        asm volatile("cp.async.commit_group;" ::: "memory")
#define CP_WAIT1()         asm volatile("cp.async.wait_group 1;" ::: "memory")

#define LDMX4(r, addr) asm volatile( \
    "ldmatrix.sync.aligned.m8n8.x4.shared.b16 {%0,%1,%2,%3}, [%4];" \
    : "=r"((r)[0]), "=r"((r)[1]), "=r"((r)[2]), "=r"((r)[3]) : "r"(addr))
#define LDMX4T(r, addr) asm volatile( \
    "ldmatrix.sync.aligned.m8n8.x4.trans.shared.b16 {%0,%1,%2,%3}, [%4];" \
    : "=r"((r)[0]), "=r"((r)[1]), "=r"((r)[2]), "=r"((r)[3]) : "r"(addr))

__device__ __forceinline__ void mma_bf16(float* c, const uint32_t* a, const uint32_t* b) {
    asm volatile(
        "mma.sync.aligned.m16n8k16.row.col.f32.bf16.bf16.f32 "
        "{%0,%1,%2,%3}, {%4,%5,%6,%7}, {%8,%9}, {%0,%1,%2,%3};"
        : "+f"(c[0]), "+f"(c[1]), "+f"(c[2]), "+f"(c[3])
        : "r"(a[0]), "r"(a[1]), "r"(a[2]), "r"(a[3]), "r"(b[0]), "r"(b[1]));
}

// ---------------- weight fp32 -> bf16 pack ---------------------------------------
__global__ __launch_bounds__(256) void pack_w_kernel(
    const float* __restrict__ in, __nv_bfloat16* __restrict__ out, int n4)
{
    const int i = blockIdx.x * 256 + threadIdx.x;
    if (i < n4) {
        const float4 v = *(const float4*)(in + (size_t)i*4);
        __nv_bfloat162 lo = __floats2bfloat162_rn(v.x, v.y);
        __nv_bfloat162 hi = __floats2bfloat162_rn(v.z, v.w);
        uint2 st;
        st.x = *(uint32_t*)&lo;
        st.y = *(uint32_t*)&hi;
        *(uint2*)(out + (size_t)i*4) = st;
    }
}

// ================================================================================
// GEMM1: G = bf16( silu(A@W1) * (A@W2) )
// ================================================================================
__global__ void __launch_bounds__(256, 2) gemm_fused_kernel(
    const __nv_bfloat16* __restrict__ A, const __nv_bfloat16* __restrict__ W1,
    const __nv_bfloat16* __restrict__ W2, __nv_bfloat16* __restrict__ G)
{
    extern __shared__ char sm[];
    const uint32_t sb = smem_u32(sm);
    const int tid = threadIdx.x;
    const int wid = tid >> 5, lane = tid & 31;
    const int wm = (wid >> 2) * 64, wn = (wid & 3) * 16;
    const int m0 = blockIdx.y * 128, n0 = blockIdx.x * 64;

    float accX[4][2][4], accG[4][2][4];
    #pragma unroll
    for (int i = 0; i < 4; i++)
        #pragma unroll
        for (int j = 0; j < 2; j++)
            #pragma unroll
            for (int v = 0; v < 4; v++) { accX[i][j][v] = 0.f; accG[i][j][v] = 0.f; }

    auto issue = [&](int st, int k0) {
        const uint32_t sA  = sb + (uint32_t)st*16384u;
        const uint32_t sB1 = sb + 49152u + (uint32_t)st*8192u;
        const uint32_t sB2 = sb + 73728u + (uint32_t)st*8192u;
        const int arow = tid >> 1;
        const __nv_bfloat16* ag = A + (size_t)(m0 + arow)*MODEL + k0 + (tid & 1)*32;
        const uint32_t abase = sA + (uint32_t)arow*128u;
        #pragma unroll
        for (int j = 0; j < 4; j++) {
            const int c = (tid & 1)*4 + j;
            CP_ASYNC(abase + (uint32_t)((c ^ (arow & 7)) << 4), ag + j*8);
        }
        const int brow = tid >> 2;
        const __nv_bfloat16* b1g = W1 + (size_t)(k0 + brow)*FFNH + n0 + (tid & 3)*16;
        const __nv_bfloat16* b2g = W2 + (size_t)(k0 + brow)*FFNH + n0 + (tid & 3)*16;
        const uint32_t b1base = sB1 + (uint32_t)brow*128u;
        const uint32_t b2base = sB2 + (uint32_t)brow*128u;
        #pragma unroll
        for (int j = 0; j < 2; j++) {
            const int c = (tid & 3)*2 + j;
            const uint32_t sw = (uint32_t)((c ^ (brow & 7)) << 4);
            CP_ASYNC(b1base + sw, b1g + j*8);
            CP_ASYNC(b2base + sw, b2g + j*8);
        }
        CP_COMMIT();
    };

    const int NT = MODEL / 64;  // 8
    issue(0, 0);
    issue(1, 64);

    auto step = [&](int kt, int cur, int nxt) {
        CP_WAIT1();
        __syncthreads();
        if (kt + 2 < NT) issue(nxt, (kt + 2)*64); else CP_COMMIT();

        const uint32_t sA  = sb + (uint32_t)cur*16384u;
        const uint32_t sB1 = sb + 49152u + (uint32_t)cur*8192u;
        const uint32_t sB2 = sb + 73728u + (uint32_t)cur*8192u;

        #pragma unroll
        for (int k16 = 0; k16 < 4; ++k16) {
            uint32_t af[4][4];
            #pragma unroll
            for (int mt = 0; mt < 4; mt++) {
                const int row = wm + mt*16 + (lane & 15);
                const uint32_t a = sA + (uint32_t)row*128u
                    + (uint32_t)((((k16*2 + (lane >> 4)) ^ (row & 7))) << 4);
                LDMX4(af[mt], a);
            }
            uint32_t b1[4], b2[4];
            {
                const int krow = k16*16 + (lane & 15);
                const int nch = (wid & 3)*2 + (lane >> 4);
                const uint32_t off = (uint32_t)krow*128u + (uint32_t)((nch ^ (lane & 7)) << 4);
                LDMX4T(b1, sB1 + off);
                LDMX4T(b2, sB2 + off);
            }
            #pragma unroll
            for (int mt = 0; mt < 4; mt++)
                #pragma unroll
                for (int nt = 0; nt < 2; nt++) {
                    mma_bf16(accX[mt][nt], af[mt], &b1[nt*2]);
                    mma_bf16(accG[mt][nt], af[mt], &b2[nt*2]);
                }
        }
    };

    for (int kt0 = 0; kt0 < NT; kt0 += 3) {
        step(kt0, 0, 2);
        if (kt0 + 1 < NT) step(kt0 + 1, 1, 0);
        if (kt0 + 2 < NT) step(kt0 + 2, 2, 1);
    }

    // epilogue: silu(X)*G -> bf16x2
    const int r = lane >> 2, q = lane & 3;
    #pragma unroll
    for (int mt = 0; mt < 4; mt++) {
        #pragma unroll
        for (int nt = 0; nt < 2; nt++) {
            const int col = n0 + wn + nt*8 + 2*q;
            #pragma unroll
            for (int half = 0; half < 2; half++) {
                const int row = m0 + wm + mt*16 + r + half*8;
                const float x0 = accX[mt][nt][half*2 + 0], g0 = accG[mt][nt][half*2 + 0];
                const float x1 = accX[mt][nt][half*2 + 1], g1 = accG[mt][nt][half*2 + 1];
                const float o0 = x0 / (1.f + __expf(-x0)) * g0;
                const float o1 = x1 / (1.f + __expf(-x1)) * g1;
                __nv_bfloat162 st = __floats2bfloat162_rn(o0, o1);
                *(__nv_bfloat162*)(G + (size_t)row*FFNH + col) = st;
            }
        }
    }
}

// ================================================================================
// GEMM2: H = A@W3 + seq  (fp32 out)
// ================================================================================
__global__ void __launch_bounds__(256, 2) gemm_out_kernel(
    const __nv_bfloat16* __restrict__ A, const __nv_bfloat16* __restrict__ W3,
    const float* __restrict__ seq, float* __restrict__ H)
{
    extern __shared__ char sm[];
    const uint32_t sb = smem_u32(sm);
    const int tid = threadIdx.x;
    const int wid = tid >> 5, lane = tid & 31;
    const int wm = (wid >> 2) * 64, wn = (wid & 3) * 32;
    const int m0 = blockIdx.y * 128, n0 = blockIdx.x * 128;

    float acc[4][4][4];
    #pragma unroll
    for (int i = 0; i < 4; i++)
        #pragma unroll
        for (int j = 0; j < 4; j++)
            #pragma unroll
            for (int v = 0; v < 4; v++) acc[i][j][v] = 0.f;

    auto issue = [&](int st, int k0) {
        const uint32_t sA = sb + (uint32_t)st*16384u;
        const uint32_t sB = sb + 49152u + (uint32_t)st*16384u;
        const int arow = tid >> 1;
        const __nv_bfloat16* ag = A + (size_t)(m0 + arow)*FFNH + k0 + (tid & 1)*32;
        const uint32_t abase = sA + (uint32_t)arow*128u;
        #pragma unroll
        for (int j = 0; j < 4; j++) {
            const int c = (tid & 1)*4 + j;
            CP_ASYNC(abase + (uint32_t)((c ^ (arow & 7)) << 4), ag + j*8);
        }
        const int brow = tid >> 2;
        const __nv_bfloat16* bg = W3 + (size_t)(k0 + brow)*MODEL + n0 + (tid & 3)*32;
        const uint32_t bbase = sB + (uint32_t)brow*256u;
        #pragma unroll
        for (int j = 0; j < 4; j++) {
            const int c = (tid & 3)*4 + j;
            CP_ASYNC(bbase + (uint32_t)((c ^ (brow & 7)) << 4), bg + j*8);
        }
        CP_COMMIT();
    };

    const int NT = FFNH / 64;  // 32
    issue(0, 0);
    issue(1, 64);

    auto step = [&](int kt, int cur, int nxt) {
        CP_WAIT1();
        __syncthreads();
        if (kt + 2 < NT) issue(nxt, (kt + 2)*64); else CP_COMMIT();

        const uint32_t sA = sb + (uint32_t)cur*16384u;
        const uint32_t sB = sb + 49152u + (uint32_t)cur*16384u;

        #pragma unroll
        for (int k16 = 0; k16 < 4; ++k16) {
            uint32_t af[4][4];
            #pragma unroll
            for (int mt = 0; mt < 4; mt++) {
                const int row = wm + mt*16 + (lane & 15);
                const uint32_t a = sA + (uint32_t)row*128u
                    + (uint32_t)((((k16*2 + (lane >> 4)) ^ (row & 7))) << 4);
                LDMX4(af[mt], a);
            }
            uint32_t bf[8];
            {
                const int krow = k16*16 + (lane & 15);
                const uint32_t rowoff = (uint32_t)krow*256u;
                #pragma unroll
                for (int hh = 0; hh < 2; hh++) {
                    const int nch = (wid & 3)*4 + hh*2 + (lane >> 4);
                    LDMX4T(&bf[hh*4], sB + rowoff + (uint32_t)((nch ^ (lane & 7)) << 4));
                }
            }
            #pragma unroll
            for (int mt = 0; mt < 4; mt++)
                #pragma unroll
                for (int nt = 0; nt < 4; nt++)
                    mma_bf16(acc[mt][nt], af[mt], &bf[nt*2]);
        }
    };

    for (int kt0 = 0; kt0 < NT; kt0 += 3) {
        step(kt0, 0, 2);
        if (kt0 + 1 < NT) step(kt0 + 1, 1, 0);
        if (kt0 + 2 < NT) step(kt0 + 2, 2, 1);
    }

    // epilogue: + seq residual
    const int r = lane >> 2, q = lane & 3;
    #pragma unroll
    for (int mt = 0; mt < 4; mt++) {
        #pragma unroll
        for (int nt = 0; nt < 4; nt++) {
            const int col = n0 + wn + nt*8 + 2*q;
            #pragma unroll
            for (int half = 0; half < 2; half++) {
                const int row = m0 + wm + mt*16 + r + half*8;
                const float2 s = *(const float2*)(seq + (size_t)row*MODEL + col);
                float2 o;
                o.x = acc[mt][nt][half*2 + 0] + s.x;
                o.y = acc[mt][nt][half*2 + 1] + s.y;
                *(float2*)(H + (size_t)row*MODEL + col) = o;
            }
        }
    }
}

// ---------------- RMSNorm: warp-per-row (fp32 in -> bf16 out) ---------------------
__global__ __launch_bounds__(128) void rmsnorm_kernel(
    const float* __restrict__ seq, const float* __restrict__ w,
    __nv_bfloat16* __restrict__ out)
{
    const int lane = threadIdx.x & 31;
    const int row = blockIdx.x * 4 + (threadIdx.x >> 5);
    const float4* x = (const float4*)(seq + (size_t)row * MODEL);

    float4 xv[4];
    float s = 0.f;
    #pragma unroll
    for (int i = 0; i < 4; i++) {
        xv[i] = x[lane + 32*i];
        s += xv[i].x*xv[i].x + xv[i].y*xv[i].y + xv[i].z*xv[i].z + xv[i].w*xv[i].w;
    }
    #pragma unroll
    for (int off = 16; off; off >>= 1) s += __shfl_xor_sync(0xffffffffu, s, off);
    const float inv = rsqrtf(s * (1.0f / MODEL) + EPSV);

    const float4* wp = (const float4*)w;
    #pragma unroll
    for (int i = 0; i < 4; i++) {
        const float4 wv = wp[lane + 32*i];
        __nv_bfloat162 o0 = __floats2bfloat162_rn(xv[i].x*inv*wv.x, xv[i].y*inv*wv.y);
        __nv_bfloat162 o1 = __floats2bfloat162_rn(xv[i].z*inv*wv.z, xv[i].w*inv*wv.w);
        uint2 st;
        st.x = *(uint32_t*)&o0;
        st.y = *(uint32_t*)&o1;
        ((uint2*)(out + (size_t)row * MODEL))[lane + 32*i] = st;
    }
}

// ---------------- fused single-query attention -------------------------------------
__global__ __launch_bounds__(128) void attn_kernel(
    const float* __restrict__ q, const float* __restrict__ h,
    const float* __restrict__ wk, const float* __restrict__ wv,
    const void* __restrict__ mask, float* __restrict__ out)
{
    const int n = blockIdx.x;
    const int b = blockIdx.y;
    const int tid = threadIdx.x;
    const int lane = tid & 31, warp = tid >> 5;

    __shared__ float q_s[64], qk_s[64], s_s[Tt], u_part[4][64], red[4];
    __shared__ int mz[4];

    // mask dtype detect (int32 0/1 => bytes 1..3 of each word are 0)
    int nz = 0;
    if (tid < 64) {
        const unsigned char* mb = (const unsigned char*)mask;
        nz = mb[4*tid + 1] | mb[4*tid + 2] | mb[4*tid + 3];
    }
    const int wany = __any_sync(0xffffffffu, nz != 0) ? 1 : 0;
    if (lane == 0) mz[warp] = wany;

    if (tid < 64) q_s[tid] = q[((size_t)b*Nh + n)*Dd + tid];
    __syncthreads();

    const int mask_int = !(mz[0] | mz[1]);

    // qk = w_k[n] @ q  (row tid, float4 loads)
    if (tid < 64) {
        const float4* wkp = (const float4*)(wk + ((size_t)n*Dd + tid)*Dd);
        float a0 = 0.f, a1 = 0.f, a2 = 0.f, a3 = 0.f;
        #pragma unroll
        for (int e = 0; e < 16; e++) {
            const float4 v = wkp[e];
            a0 = fmaf(v.x, q_s[4*e+0], a0);
            a1 = fmaf(v.y, q_s[4*e+1], a1);
            a2 = fmaf(v.z, q_s[4*e+2], a2);
            a3 = fmaf(v.w, q_s[4*e+3], a3);
        }
        qk_s[tid] = (a0 + a1) + (a2 + a3);
    }
    __syncthreads();

    const float scale = 0.125f;

    // scores: one full 64-dot per thread, high MLP
    for (int t = tid; t < Tt; t += 128) {
        const float4* hp = (const float4*)(h + ((size_t)(b*Tt + t))*MODEL + n*Dd);
        float a0 = 0.f, a1 = 0.f, a2 = 0.f, a3 = 0.f;
        #pragma unroll
        for (int e = 0; e < 16; e++) {
            const float4 v = hp[e];
            a0 = fmaf(v.x, qk_s[4*e+0], a0);
            a1 = fmaf(v.y, qk_s[4*e+1], a1);
            a2 = fmaf(v.z, qk_s[4*e+2], a2);
            a3 = fmaf(v.w, qk_s[4*e+3], a3);
        }
        const float p = (a0 + a1) + (a2 + a3);
        bool m;
        if (mask_int) m = ((const int*)mask)[b*Tt + t] != 0;
        else          m = ((const unsigned char*)mask)[b*Tt + t] != 0;
        s_s[t] = m ? p * scale : -INFINITY;
    }
    __syncthreads();

    // softmax max
    float lm = -INFINITY;
    for (int t = tid; t < Tt; t += 128) lm = fmaxf(lm, s_s[t]);
    #pragma unroll
    for (int off = 16; off; off >>= 1) lm = fmaxf(lm, __shfl_xor_sync(0xffffffffu, lm, off));
    if (lane == 0) red[warp] = lm;
    __syncthreads();
    const float mx = fmaxf(fmaxf(red[0], red[1]), fmaxf(red[2], red[3]));

    // exp + sum
    float ls = 0.0f;
    for (int t = tid; t < Tt; t += 128) {
        float e = __expf(s_s[t] - mx);
        s_s[t] = e;
        ls += e;
    }
    #pragma unroll
    for (int off = 16; off; off >>= 1) ls += __shfl_xor_sync(0xffffffffu, ls, off);
    __syncthreads();   // protect red[] reuse
    if (lane == 0) red[warp] = ls;
    __syncthreads();
    const float inv = 1.0f / (red[0] + red[1] + red[2] + red[3]);

    // u[d] = sum_t attn[t]*h[t,d]  (float2 per thread, 4 t-chunks)
    const int d2 = (tid & 31), chunk = tid >> 5;
    float2 acc = make_float2(0.f, 0.f);
    for (int t = chunk; t < Tt; t += 4) {
        const float w8 = s_s[t];
        const float2 v = *(const float2*)(h + ((size_t)(b*Tt + t))*MODEL + n*Dd + d2*2);
        acc.x = fmaf(w8, v.x, acc.x);
        acc.y = fmaf(w8, v.y, acc.y);
    }
    u_part[chunk][d2*2]   = acc.x;
    u_part[chunk][d2*2+1] = acc.y;
    __syncthreads();

    // ctx = u @ w_v[n]; out = ctx + q
    if (tid < 64) {
        const float u = (u_part[0][tid] + u_part[1][tid] + u_part[2][tid] + u_part[3][tid]) * inv;
        q_s[tid] += 0.f;  // keep q_s live
        // store u back for the matvec
        qk_s[tid] = u;
    }
    __syncthreads();
    if (tid < 64) {
        float c = 0.0f;
        const float* wvp = wv + (size_t)n*Dd*Dd + tid;
        #pragma unroll
        for (int dd = 0; dd < 64; dd++) c = fmaf(qk_s[dd], wvp[dd*Dd], c);
        out[((size_t)b*Nh + n)*Dd + tid] = c + q_s[tid];
    }
}

// ---------------- launch -------------------------------------------------------------
extern "C" void kernel_launch(void* const* d_in, const int* in_sizes, int n_in,
                              void* d_out, int out_size)
{
    const float* q    = (const float*)d_in[0];
    const float* seq  = (const float*)d_in[1];
    const float* rmsw = (const float*)d_in[2];
    const float* w1   = (const float*)d_in[3];
    const float* w2   = (const float*)d_in[4];
    const float* w3   = (const float*)d_in[5];
    const float* wk   = (const float*)d_in[6];
    const float* wv   = (const float*)d_in[7];
    const void*  msk  = d_in[8];
    float* out = (float*)d_out;

    __nv_bfloat16 *snb, *g, *w1b, *w2b, *w3b;
    float *h;
    cudaGetSymbolAddress((void**)&snb, d_snb);
    cudaGetSymbolAddress((void**)&g,   d_g);
    cudaGetSymbolAddress((void**)&h,   d_h);
    cudaGetSymbolAddress((void**)&w1b, d_w1b);
    cudaGetSymbolAddress((void**)&w2b, d_w2b);
    cudaGetSymbolAddress((void**)&w3b, d_w3b);

    const int SMEM = 98304;
    cudaFuncSetAttribute(gemm_fused_kernel, cudaFuncAttributeMaxDynamicSharedMemorySize, SMEM);
    cudaFuncSetAttribute(gemm_out_kernel,   cudaFuncAttributeMaxDynamicSharedMemorySize, SMEM);

    const int W4 = (MODEL*FFNH)/4;
    pack_w_kernel<<<(W4 + 255)/256, 256>>>(w1, w1b, W4);
    pack_w_kernel<<<(W4 + 255)/256, 256>>>(w2, w2b, W4);
    pack_w_kernel<<<(W4 + 255)/256, 256>>>(w3, w3b, W4);

    rmsnorm_kernel<<<ROWS/4, 128>>>(seq, rmsw, snb);
    gemm_fused_kernel<<<dim3(FFNH/64, ROWS/128), 256, SMEM>>>(snb, w1b, w2b, g);
    gemm_out_kernel<<<dim3(MODEL/128, ROWS/128), 256, SMEM>>>(g, w3b, seq, h);
    attn_kernel<<<dim3(Nh, Bb), 128>>>(q, h, wk, wv, msk, out);
}